// round 8
// baseline (speedup 1.0000x reference)
#include <cuda_runtime.h>

// SSIM, fully fused, single kernel. X,Y: f32[32,3,512,512] -> scalar mean SSIM.
//
// Key trick: X and Y use IDENTICAL Gaussian weights -> pack {x,y} and {x^2,y^2}
// into f32x2 lanes through BOTH conv passes. Weights are broadcast pairs {w,w}
// (6 registers-pairs total, shared by both phases).
//
// TW=64 x TH=32, smem planes: mu u64[42][64] + sq u64[42][64] + xy f32[42][64]
// = 53.76KB -> 4 CTAs/SM (32 warps), 64 regs/thread.
// Phase 1 (16 col-quads x 16 rows): horizontal 11-tap conv; mu-pair + sq-pair
//   chains in fma2, xy chain scalar FFMA-imm.
// Phase 2 (32 col-pairs x 8 row-groups): vertical 11-tap conv; all chains fma2
//   (xy pairs across columns), 42 LDS/thread (2x LDS.128 + 1x LDS.64 per tap).
// Epilogue folds [-1,1]->[0,1]: mu' = (mu+1)/2, sigma' = sigma/4.
// Block partials -> __device__ array; last block reduces, writes scalar, resets.

#define TW 64
#define TH 32
#define NHR (TH + 10)   // 42
#define NTHR 256
#define GX 8
#define GY 16
#define GZ 96
#define NBLOCKS (GX * GY * GZ)

#define MU_OFF 0
#define SQ_OFF (NHR * TW * 8)            // 21504
#define XY_OFF (2 * NHR * TW * 8)        // 43008
#define SMEM_BYTES (2 * NHR * TW * 8 + NHR * TW * 4)  // 53760

typedef unsigned long long u64;

__device__ float g_partials[NBLOCKS];
__device__ unsigned int g_count = 0;

// scalar: acc += v * w[k], w[k] immediate multiplier (FFMA-imm, rt=1).
__device__ __forceinline__ void fmaw(const int k, const float v, float& a) {
    switch (k) {
    case 0:  asm("fma.rn.f32 %0, %1, 0f3A86CAB5, %0;" : "+f"(a) : "f"(v)); break;
    case 1:  asm("fma.rn.f32 %0, %1, 0f3BF8FF05, %0;" : "+f"(a) : "f"(v)); break;
    case 2:  asm("fma.rn.f32 %0, %1, 0f3D137590, %0;" : "+f"(a) : "f"(v)); break;
    case 3:  asm("fma.rn.f32 %0, %1, 0f3DDFF883, %0;" : "+f"(a) : "f"(v)); break;
    case 4:  asm("fma.rn.f32 %0, %1, 0f3E5A1E20, %0;" : "+f"(a) : "f"(v)); break;
    case 5:  asm("fma.rn.f32 %0, %1, 0f3E8832B1, %0;" : "+f"(a) : "f"(v)); break;
    case 6:  asm("fma.rn.f32 %0, %1, 0f3E5A1E20, %0;" : "+f"(a) : "f"(v)); break;
    case 7:  asm("fma.rn.f32 %0, %1, 0f3DDFF883, %0;" : "+f"(a) : "f"(v)); break;
    case 8:  asm("fma.rn.f32 %0, %1, 0f3D137590, %0;" : "+f"(a) : "f"(v)); break;
    case 9:  asm("fma.rn.f32 %0, %1, 0f3BF8FF05, %0;" : "+f"(a) : "f"(v)); break;
    case 10: asm("fma.rn.f32 %0, %1, 0f3A86CAB5, %0;" : "+f"(a) : "f"(v)); break;
    default: break;
    }
}

__device__ __forceinline__ u64 pk2(float lo, float hi) {
    u64 r;
    asm("mov.b64 %0, {%1, %2};" : "=l"(r) : "f"(lo), "f"(hi));
    return r;
}
__device__ __forceinline__ void upk2(float& lo, float& hi, u64 v) {
    asm("mov.b64 {%0, %1}, %2;" : "=f"(lo), "=f"(hi) : "l"(v));
}
__device__ __forceinline__ u64 fma2(u64 a, u64 b, u64 c) {
    u64 d;
    asm("fma.rn.f32x2 %0, %1, %2, %3;" : "=l"(d) : "l"(a), "l"(b), "l"(c));
    return d;
}
__device__ __forceinline__ u64 mul2(u64 a, u64 b) {
    u64 d;
    asm("mul.rn.f32x2 %0, %1, %2;" : "=l"(d) : "l"(a), "l"(b));
    return d;
}

// Gaussian(11, sigma=1.5) weights.
__device__ __host__ __forceinline__ constexpr float gwe(int k) {
    return (k == 0 || k == 10) ? 0.00102838f
         : (k == 1 || k == 9)  ? 0.00759876f
         : (k == 2 || k == 8)  ? 0.03600079f
         : (k == 3 || k == 7)  ? 0.10936072f
         : (k == 4 || k == 6)  ? 0.21300555f
         : (k == 5)            ? 0.26601173f
         : 0.0f;
}

__global__ void __launch_bounds__(NTHR, 4)
ssim_main_kernel(const float* __restrict__ X, const float* __restrict__ Y,
                 float* __restrict__ out, double inv_count) {
    extern __shared__ char shb[];
    u64*   sh_mu = reinterpret_cast<u64*>(shb + MU_OFF);   // [NHR][TW] {hx,hy}
    u64*   sh_sq = reinterpret_cast<u64*>(shb + SQ_OFF);   // [NHR][TW] {hxx,hyy}
    float* sh_xy = reinterpret_cast<float*>(shb + XY_OFF); // [NHR][TW] hxy

    const int tid = threadIdx.x;
    const int c0 = blockIdx.x * TW;
    const int r0 = blockIdx.y * TH;
    const long img = blockIdx.z;
    const float* __restrict__ Xi = X + img * (512L * 512L);
    const float* __restrict__ Yi = Y + img * (512L * 512L);

    // Broadcast weight pairs {w,w}, symmetric: only 6 held.
    u64 WB[6];
#pragma unroll
    for (int k = 0; k < 6; k++) WB[k] = pk2(gwe(k), gwe(k));

    // ---------------- Phase 1: horizontal pass into smem ----------------
    {
        const int q1 = tid & 15;
        const int r1 = tid >> 4;
        const int basec = c0 + 4 * q1;
        for (int hr = r1; hr < NHR; hr += 16) {
            const int gr = r0 + hr;
            const float* __restrict__ xr = Xi + (long)gr * 512;
            const float* __restrict__ yr = Yi + (long)gr * 512;
            const bool rok = (gr < 512);
            float xv[16], yv[16];
#pragma unroll
            for (int q = 0; q < 4; q++) {
                const int qc = basec + 4 * q;
                float4 xq, yq;
                if (rok && qc < 512) {
                    xq = *reinterpret_cast<const float4*>(xr + qc);
                    yq = *reinterpret_cast<const float4*>(yr + qc);
                } else {
                    xq = make_float4(0.f, 0.f, 0.f, 0.f);
                    yq = make_float4(0.f, 0.f, 0.f, 0.f);
                }
                xv[4 * q + 0] = xq.x; xv[4 * q + 1] = xq.y;
                xv[4 * q + 2] = xq.z; xv[4 * q + 3] = xq.w;
                yv[4 * q + 0] = yq.x; yv[4 * q + 1] = yq.y;
                yv[4 * q + 2] = yq.z; yv[4 * q + 3] = yq.w;
            }
            u64 zac[4], sac[4];
            float xyac[4];
#pragma unroll
            for (int j = 0; j < 4; j++) { zac[j] = 0ull; sac[j] = 0ull; xyac[j] = 0.f; }
#pragma unroll
            for (int t = 0; t < 14; t++) {
                const float xt = xv[t], yt = yv[t];
                const u64 xyp = pk2(xt, yt);         // {x, y}
                const u64 sqp = mul2(xyp, xyp);      // {x^2, y^2}
                const float pxy = xt * yt;
#pragma unroll
                for (int j = 0; j < 4; j++) {
                    const int k = t - j;
                    if (k >= 0 && k <= 10) {
                        const u64 w = WB[k <= 5 ? k : 10 - k];
                        zac[j] = fma2(xyp, w, zac[j]);
                        sac[j] = fma2(sqp, w, sac[j]);
                        fmaw(k, pxy, xyac[j]);
                    }
                }
            }
            const int so = hr * TW + 4 * q1;
            *reinterpret_cast<ulonglong2*>(&sh_mu[so])     = make_ulonglong2(zac[0], zac[1]);
            *reinterpret_cast<ulonglong2*>(&sh_mu[so + 2]) = make_ulonglong2(zac[2], zac[3]);
            *reinterpret_cast<ulonglong2*>(&sh_sq[so])     = make_ulonglong2(sac[0], sac[1]);
            *reinterpret_cast<ulonglong2*>(&sh_sq[so + 2]) = make_ulonglong2(sac[2], sac[3]);
            *reinterpret_cast<float4*>(&sh_xy[so]) = make_float4(xyac[0], xyac[1], xyac[2], xyac[3]);
        }
    }
    __syncthreads();

    // ---------------- Phase 2: vertical conv, 4 vrows x 2 cols, all fma2 --------
    const int tx2 = tid & 31;
    const int ty2 = tid >> 5;
    const int lr0 = ty2 * 4;
    const int scol = 2 * tx2;

    u64 amu[4][2], asq[4][2], axy[4];  // amu/asq: [vrow][col]{map pair}; axy: {c0,c1}
#pragma unroll
    for (int v = 0; v < 4; v++) {
        amu[v][0] = 0ull; amu[v][1] = 0ull;
        asq[v][0] = 0ull; asq[v][1] = 0ull;
        axy[v] = 0ull;
    }

#pragma unroll
    for (int i = 0; i < 14; i++) {
        const int roff = (lr0 + i) * TW + scol;
        const ulonglong2 m = *reinterpret_cast<const ulonglong2*>(&sh_mu[roff]);
        const ulonglong2 s = *reinterpret_cast<const ulonglong2*>(&sh_sq[roff]);
        const u64 x2 = *reinterpret_cast<const u64*>(&sh_xy[roff]);
#pragma unroll
        for (int v = 0; v < 4; v++) {
            const int k = i - v;
            if (k >= 0 && k <= 10) {
                const u64 w = WB[k <= 5 ? k : 10 - k];
                amu[v][0] = fma2(m.x, w, amu[v][0]);
                amu[v][1] = fma2(m.y, w, amu[v][1]);
                asq[v][0] = fma2(s.x, w, asq[v][0]);
                asq[v][1] = fma2(s.y, w, asq[v][1]);
                axy[v]    = fma2(x2,  w, axy[v]);
            }
        }
    }

    // ---------------- Epilogue + reduction ----------------
    float lsum = 0.0f;
    const float C1 = 1e-4f;      // (0.01)^2
    const float C2x4 = 0.0036f;  // 4*(0.03)^2
#pragma unroll
    for (int v = 0; v < 4; v++) {
        const int orow = r0 + lr0 + v;
        float xyc0, xyc1;
        upk2(xyc0, xyc1, axy[v]);
#pragma unroll
        for (int c = 0; c < 2; c++) {
            const int ocol = c0 + scol + c;
            float m1, m2, xx, yy;
            upk2(m1, m2, amu[v][c]);
            upk2(xx, yy, asq[v][c]);
            const float xy = c ? xyc1 : xyc0;
            const float s1  = fmaf(-m1, m1, xx);
            const float s2  = fmaf(-m2, m2, yy);
            const float s12 = fmaf(-m1, m2, xy);
            const float m1p = fmaf(0.5f, m1, 0.5f);
            const float m2p = fmaf(0.5f, m2, 0.5f);
            const float csn = fmaf(2.0f, s12, C2x4);
            const float csd = s1 + s2 + C2x4;
            const float t = m1p * m2p;
            const float ln = fmaf(2.0f, t, C1);
            const float ld = fmaf(m1p, m1p, fmaf(m2p, m2p, C1));
            const float ssim = (csn * ln) * __fdividef(1.0f, csd * ld);
            lsum += (orow < 502 && ocol < 502) ? ssim : 0.0f;
        }
    }

#pragma unroll
    for (int off = 16; off > 0; off >>= 1)
        lsum += __shfl_xor_sync(0xffffffffu, lsum, off);

    __shared__ float wsum[8];
    __shared__ bool is_last;
    const int wid = tid >> 5;
    const int lid = tid & 31;
    if (lid == 0) wsum[wid] = lsum;
    __syncthreads();
    if (tid == 0) {
        float b = 0.0f;
#pragma unroll
        for (int w = 0; w < 8; w++) b += wsum[w];
        const int bi = blockIdx.x + gridDim.x * (blockIdx.y + gridDim.y * blockIdx.z);
        g_partials[bi] = b;
        __threadfence();
        const unsigned int n = atomicAdd(&g_count, 1u);
        is_last = (n == (unsigned int)(NBLOCKS - 1));
    }
    __syncthreads();

    if (is_last) {
        __threadfence();
        double s = 0.0;
        for (int i = tid; i < NBLOCKS; i += NTHR)
            s += (double)g_partials[i];
#pragma unroll
        for (int off = 16; off > 0; off >>= 1)
            s += __shfl_xor_sync(0xffffffffu, s, off);
        __shared__ double sd[8];
        if (lid == 0) sd[wid] = s;
        __syncthreads();
        if (tid == 0) {
            double tot = 0.0;
#pragma unroll
            for (int w = 0; w < 8; w++) tot += sd[w];
            out[0] = (float)(tot * inv_count);
            g_count = 0;  // reset for next graph replay
        }
    }
}

extern "C" void kernel_launch(void* const* d_in, const int* in_sizes, int n_in,
                              void* d_out, int out_size) {
    const float* X = (const float*)d_in[0];
    const float* Y = (const float*)d_in[1];
    float* out = (float*)d_out;

    const int images = in_sizes[0] / (512 * 512);  // 96
    const double count = (double)images * 502.0 * 502.0;

    cudaFuncSetAttribute(ssim_main_kernel,
                         cudaFuncAttributeMaxDynamicSharedMemorySize, SMEM_BYTES);

    dim3 grid(GX, GY, images);  // 12288 blocks
    ssim_main_kernel<<<grid, NTHR, SMEM_BYTES>>>(X, Y, out, 1.0 / count);
}